// round 1
// baseline (speedup 1.0000x reference)
#include <cuda_runtime.h>
#include <math.h>

// Problem constants (fixed by the dataset)
#define BDIM   4096          // d_model
#define SEQ    2048          // sequence length
#define NBATCH 2
#define MTOK   (NBATCH*SEQ)  // 4096 total tokens

// ---------------------------------------------------------------------------
// Scratch (static __device__ arrays: no cudaMalloc anywhere)
// ---------------------------------------------------------------------------
__device__ float g_xA[(size_t)NBATCH*SEQ*BDIM];          // 64 MB
__device__ float g_xB[(size_t)NBATCH*SEQ*BDIM];          // 64 MB
__device__ float g_sc[(size_t)NBATCH*BDIM*BDIM];         // 128 MB (scores -> attn in place)
__device__ float g_xO[(size_t)NBATCH*SEQ*BDIM];          // 64 MB
__device__ float g_t [(size_t)NBATCH*SEQ*BDIM];          // 64 MB (x + silu MLP)

// ---------------------------------------------------------------------------
// Generic fp32 tiled GEMM: C[m,n] = sum_k A(m,k) * B(k,n)  (+ epilogue)
//   A_KM=false: A(m,k) = A[m*lda + k]   (row-major [M,K])
//   A_KM=true : A(m,k) = A[k*lda + m]   (K-major   [K,M])  -- for the TN scores GEMM
//   B_KN=true : B(k,n) = B[k*ldb + n]   ([K,N])            -- NN / TN
//   B_KN=false: B(k,n) = B[n*ldb + k]   ([N,K])            -- NT (torch Linear weights)
// EPI: 0 = store, 1 = +bias, 2 = resid + silu(acc + bias)
// Tiles: BM=BN=128, BK=16, 256 threads, 8x8 per-thread micro-tile.
// Assumes M,N multiples of 128 and K multiple of 16 (true for all calls here).
// ---------------------------------------------------------------------------
template<bool A_KM, bool B_KN, int EPI>
__global__ __launch_bounds__(256, 2)
void gemm128(const float* __restrict__ Ag, const float* __restrict__ Bg,
             float* __restrict__ Cg,
             int K, int lda, int ldb, int ldc,
             long sA, long sB, long sC,
             const float* __restrict__ bias,
             const float* __restrict__ resid)
{
    constexpr int BM = 128, BN = 128, BK = 16;
    __shared__ __align__(16) float As[BK][BM];
    __shared__ __align__(16) float Bs[BK][BN];

    const int bz = blockIdx.z;
    const float* A = Ag + (long)bz * sA;
    const float* B = Bg + (long)bz * sB;
    float*       C = Cg + (long)bz * sC;

    const int m0  = blockIdx.y * BM;
    const int n0  = blockIdx.x * BN;
    const int tid = threadIdx.x;

    const int tm = (tid >> 4) << 3;   // 0..120
    const int tn = (tid & 15) << 3;   // 0..120

    float acc[8][8];
#pragma unroll
    for (int i = 0; i < 8; i++)
#pragma unroll
        for (int j = 0; j < 8; j++) acc[i][j] = 0.f;

    for (int k0 = 0; k0 < K; k0 += BK) {
        // ---- stage A tile ----
#pragma unroll
        for (int r = 0; r < 2; r++) {
            int i = tid + r * 256;            // float4 index 0..511
            if (A_KM) {
                int ak = i >> 5;              // 0..15
                int am = (i & 31) << 2;       // 0..124
                float4 v = *reinterpret_cast<const float4*>(
                    &A[(long)(k0 + ak) * lda + m0 + am]);
                *reinterpret_cast<float4*>(&As[ak][am]) = v;
            } else {
                int am = i >> 2;              // 0..127
                int ak = (i & 3) << 2;        // 0,4,8,12
                float4 v = *reinterpret_cast<const float4*>(
                    &A[(long)(m0 + am) * lda + k0 + ak]);
                As[ak + 0][am] = v.x; As[ak + 1][am] = v.y;
                As[ak + 2][am] = v.z; As[ak + 3][am] = v.w;
            }
        }
        // ---- stage B tile ----
#pragma unroll
        for (int r = 0; r < 2; r++) {
            int i = tid + r * 256;
            if (B_KN) {
                int bk = i >> 5;
                int bn = (i & 31) << 2;
                float4 v = *reinterpret_cast<const float4*>(
                    &B[(long)(k0 + bk) * ldb + n0 + bn]);
                *reinterpret_cast<float4*>(&Bs[bk][bn]) = v;
            } else {
                int bn = i >> 2;
                int bk = (i & 3) << 2;
                float4 v = *reinterpret_cast<const float4*>(
                    &B[(long)(n0 + bn) * ldb + k0 + bk]);
                Bs[bk + 0][bn] = v.x; Bs[bk + 1][bn] = v.y;
                Bs[bk + 2][bn] = v.z; Bs[bk + 3][bn] = v.w;
            }
        }
        __syncthreads();

#pragma unroll
        for (int k = 0; k < BK; k++) {
            float4 a0 = *reinterpret_cast<const float4*>(&As[k][tm]);
            float4 a1 = *reinterpret_cast<const float4*>(&As[k][tm + 4]);
            float4 b0 = *reinterpret_cast<const float4*>(&Bs[k][tn]);
            float4 b1 = *reinterpret_cast<const float4*>(&Bs[k][tn + 4]);
            float a[8] = {a0.x, a0.y, a0.z, a0.w, a1.x, a1.y, a1.z, a1.w};
            float b[8] = {b0.x, b0.y, b0.z, b0.w, b1.x, b1.y, b1.z, b1.w};
#pragma unroll
            for (int i = 0; i < 8; i++)
#pragma unroll
                for (int j = 0; j < 8; j++)
                    acc[i][j] += a[i] * b[j];
        }
        __syncthreads();
    }

    // ---- epilogue ----
#pragma unroll
    for (int i = 0; i < 8; i++) {
        long row = (long)(m0 + tm + i);
#pragma unroll
        for (int j = 0; j < 8; j += 4) {
            int col = n0 + tn + j;
            float4 v;
            v.x = acc[i][j + 0]; v.y = acc[i][j + 1];
            v.z = acc[i][j + 2]; v.w = acc[i][j + 3];
            if (EPI >= 1) {
                float4 bb = *reinterpret_cast<const float4*>(&bias[col]);
                v.x += bb.x; v.y += bb.y; v.z += bb.z; v.w += bb.w;
            }
            if (EPI == 2) {
                float4 rr = *reinterpret_cast<const float4*>(&resid[row * ldc + col]);
                v.x = rr.x + v.x / (1.f + expf(-v.x));
                v.y = rr.y + v.y / (1.f + expf(-v.y));
                v.z = rr.z + v.z / (1.f + expf(-v.z));
                v.w = rr.w + v.w / (1.f + expf(-v.w));
            }
            *reinterpret_cast<float4*>(&C[row * ldc + col]) = v;
        }
    }
}

// ---------------------------------------------------------------------------
// Row softmax, in place. One CTA per row of 4096 floats, 256 threads.
// ---------------------------------------------------------------------------
__global__ __launch_bounds__(256)
void softmax_rows(float* __restrict__ sc)
{
    __shared__ float sred[32];
    float* p = sc + (long)blockIdx.x * BDIM;
    const int tid = threadIdx.x;

    float v[16];
    float m = -3.0e38f;
#pragma unroll
    for (int i = 0; i < 16; i++) {
        v[i] = p[tid + 256 * i];
        m = fmaxf(m, v[i]);
    }
#pragma unroll
    for (int o = 16; o > 0; o >>= 1) m = fmaxf(m, __shfl_xor_sync(0xffffffffu, m, o));
    if ((tid & 31) == 0) sred[tid >> 5] = m;
    __syncthreads();
    if (tid < 32) {
        float t = (tid < 8) ? sred[tid] : -3.0e38f;
#pragma unroll
        for (int o = 4; o > 0; o >>= 1) t = fmaxf(t, __shfl_xor_sync(0xffffffffu, t, o));
        if (tid == 0) sred[0] = t;
    }
    __syncthreads();
    m = sred[0];

    float s = 0.f;
#pragma unroll
    for (int i = 0; i < 16; i++) { v[i] = expf(v[i] - m); s += v[i]; }
#pragma unroll
    for (int o = 16; o > 0; o >>= 1) s += __shfl_xor_sync(0xffffffffu, s, o);
    __syncthreads();                       // sred[0] consumed by all threads above
    if ((tid & 31) == 0) sred[tid >> 5] = s;
    __syncthreads();
    if (tid < 32) {
        float t = (tid < 8) ? sred[tid] : 0.f;
#pragma unroll
        for (int o = 4; o > 0; o >>= 1) t += __shfl_xor_sync(0xffffffffu, t, o);
        if (tid == 0) sred[0] = t;
    }
    __syncthreads();
    float inv = 1.0f / sred[0];
#pragma unroll
    for (int i = 0; i < 16; i++) p[tid + 256 * i] = v[i] * inv;
}

// ---------------------------------------------------------------------------
// Launcher (graph-capturable: plain launches + symbol-address queries only)
// ---------------------------------------------------------------------------
extern "C" void kernel_launch(void* const* d_in, const int* in_sizes, int n_in,
                              void* d_out, int out_size)
{
    const float* x    = (const float*)d_in[0];
    const float* W1   = (const float*)d_in[1];
    const float* W2   = (const float*)d_in[2];
    const float* W4   = (const float*)d_in[3];
    const float* b4   = (const float*)d_in[4];
    const float* Wout = (const float*)d_in[5];
    const float* bout = (const float*)d_in[6];
    float* out = (float*)d_out;

    float *xA, *xB, *sc, *xO, *t;
    cudaGetSymbolAddress((void**)&xA, g_xA);
    cudaGetSymbolAddress((void**)&xB, g_xB);
    cudaGetSymbolAddress((void**)&sc, g_sc);
    cudaGetSymbolAddress((void**)&xO, g_xO);
    cudaGetSymbolAddress((void**)&t,  g_t);

    dim3 blk(256, 1, 1);

    // 1) xA = x @ W1^T ; xB = x @ W2^T    (NT, M=4096 N=4096 K=4096)
    {
        dim3 g(BDIM / 128, MTOK / 128, 1);
        gemm128<false, false, 0><<<g, blk>>>(x, W1, xA, BDIM, BDIM, BDIM, BDIM,
                                             0, 0, 0, nullptr, nullptr);
        gemm128<false, false, 0><<<g, blk>>>(x, W2, xB, BDIM, BDIM, BDIM, BDIM,
                                             0, 0, 0, nullptr, nullptr);
    }

    // 2) scores[b] = xA[b]^T @ xB[b]      (TN, M=N=4096, K=2048, batched)
    {
        dim3 g(BDIM / 128, BDIM / 128, NBATCH);
        gemm128<true, true, 0><<<g, blk>>>(xA, xB, sc, SEQ, BDIM, BDIM, BDIM,
                                           (long)SEQ * BDIM, (long)SEQ * BDIM,
                                           (long)BDIM * BDIM, nullptr, nullptr);
    }

    // 3) attn = softmax(scores) rows, in place
    softmax_rows<<<NBATCH * BDIM, 256>>>(sc);

    // 4) xO[b] = x[b] @ attn[b]           (NN, M=2048 N=4096 K=4096, batched)
    {
        dim3 g(BDIM / 128, SEQ / 128, NBATCH);
        gemm128<false, true, 0><<<g, blk>>>(x, sc, xO, BDIM, BDIM, BDIM, BDIM,
                                            (long)SEQ * BDIM, (long)BDIM * BDIM,
                                            (long)SEQ * BDIM, nullptr, nullptr);
    }

    // 5) t = x + silu(xO @ W4^T + b4)     (NT + fused epilogue)
    {
        dim3 g(BDIM / 128, MTOK / 128, 1);
        gemm128<false, false, 2><<<g, blk>>>(xO, W4, t, BDIM, BDIM, BDIM, BDIM,
                                             0, 0, 0, b4, x);
        // 6) out = t @ Wout^T + bout      (NT + bias)
        gemm128<false, false, 1><<<g, blk>>>(t, Wout, out, BDIM, BDIM, BDIM, BDIM,
                                             0, 0, 0, bout, nullptr);
    }
}

// round 2
// speedup vs baseline: 2.7491x; 2.7491x over previous
#include <cuda_runtime.h>
#include <cuda_bf16.h>
#include <math.h>

#define BDIM 4096
#define SEQ  2048
#define NB   2
#define MTOK 4096

typedef unsigned int u32;

// ---------------------------------------------------------------------------
// Static scratch (no runtime allocation anywhere)
// ---------------------------------------------------------------------------
__device__ float g_xA[(size_t)NB * SEQ * BDIM];    // fp32 xA (needs transpose)
__device__ float g_sc[(size_t)NB * BDIM * BDIM];   // fp32 scores

static const size_t PLANE_X  = (size_t)MTOK * BDIM;      // 16.7M
static const size_t PLANE_W  = (size_t)BDIM * BDIM;      // 16.7M
static const size_t PLANE_AT = (size_t)NB * BDIM * SEQ;  // 16.7M
static const size_t PLANE_SC = (size_t)NB * BDIM * BDIM; // 33.5M

__device__ __nv_bfloat16 s_x  [2 * PLANE_X];   // x split (hi plane, lo plane)
__device__ __nv_bfloat16 s_w1 [2 * PLANE_W];   // W1^T split
__device__ __nv_bfloat16 s_w2 [2 * PLANE_W];
__device__ __nv_bfloat16 s_w4 [2 * PLANE_W];
__device__ __nv_bfloat16 s_wo [2 * PLANE_W];
__device__ __nv_bfloat16 s_xAT[2 * PLANE_AT];  // xA^T split [b][D][S]
__device__ __nv_bfloat16 s_xB [2 * PLANE_X];   // xB split [b][S][D]
__device__ __nv_bfloat16 s_at [2 * PLANE_SC];  // attn split [b][D][D]
__device__ __nv_bfloat16 s_xO [2 * PLANE_X];   // xO split
__device__ __nv_bfloat16 s_t  [2 * PLANE_X];   // (x + silu mlp) split

// ---------------------------------------------------------------------------
// helpers
// ---------------------------------------------------------------------------
__device__ __forceinline__ void split2(float v, __nv_bfloat16& h, __nv_bfloat16& l) {
    h = __float2bfloat16(v);
    l = __float2bfloat16(v - __bfloat162float(h));
}

__device__ __forceinline__ void cpa16(u32 dst, const void* src) {
    asm volatile("cp.async.cg.shared.global [%0], [%1], 16;\n" :: "r"(dst), "l"(src));
}
__device__ __forceinline__ void cp_commit() { asm volatile("cp.async.commit_group;\n"); }
__device__ __forceinline__ void cp_wait1()  { asm volatile("cp.async.wait_group 1;\n"); }

__device__ __forceinline__ void ldsm_x4(u32* r, u32 addr) {
    asm volatile("ldmatrix.sync.aligned.m8n8.x4.shared.b16 {%0,%1,%2,%3}, [%4];\n"
                 : "=r"(r[0]), "=r"(r[1]), "=r"(r[2]), "=r"(r[3]) : "r"(addr));
}
__device__ __forceinline__ void ldsm_x4t(u32* r, u32 addr) {
    asm volatile("ldmatrix.sync.aligned.m8n8.x4.trans.shared.b16 {%0,%1,%2,%3}, [%4];\n"
                 : "=r"(r[0]), "=r"(r[1]), "=r"(r[2]), "=r"(r[3]) : "r"(addr));
}
__device__ __forceinline__ void mma16816(float* d, const u32* a, const u32* b) {
    asm volatile("mma.sync.aligned.m16n8k16.row.col.f32.bf16.bf16.f32 "
                 "{%0,%1,%2,%3}, {%4,%5,%6,%7}, {%8,%9}, {%0,%1,%2,%3};\n"
                 : "+f"(d[0]), "+f"(d[1]), "+f"(d[2]), "+f"(d[3])
                 : "r"(a[0]), "r"(a[1]), "r"(a[2]), "r"(a[3]), "r"(b[0]), "r"(b[1]));
}

// ---------------------------------------------------------------------------
// split kernels
// ---------------------------------------------------------------------------
__global__ void split_rm(const float* __restrict__ in,
                         __nv_bfloat16* __restrict__ hi,
                         __nv_bfloat16* __restrict__ lo, size_t n4)
{
    size_t i = (size_t)blockIdx.x * blockDim.x + threadIdx.x;
    if (i >= n4) return;
    float4 v = reinterpret_cast<const float4*>(in)[i];
    __nv_bfloat16 h0,l0,h1,l1,h2,l2,h3,l3;
    split2(v.x,h0,l0); split2(v.y,h1,l1); split2(v.z,h2,l2); split2(v.w,h3,l3);
    reinterpret_cast<__nv_bfloat162*>(hi)[2*i+0] = __halves2bfloat162(h0,h1);
    reinterpret_cast<__nv_bfloat162*>(hi)[2*i+1] = __halves2bfloat162(h2,h3);
    reinterpret_cast<__nv_bfloat162*>(lo)[2*i+0] = __halves2bfloat162(l0,l1);
    reinterpret_cast<__nv_bfloat162*>(lo)[2*i+1] = __halves2bfloat162(l2,l3);
}

// in: [R,C] fp32 -> out hi/lo: [C,R] bf16   (batched via blockIdx.z, stride R*C)
__global__ void split_tr(const float* __restrict__ in,
                         __nv_bfloat16* __restrict__ hi,
                         __nv_bfloat16* __restrict__ lo, int R, int C)
{
    __shared__ float tile[32][33];
    size_t boff = (size_t)blockIdx.z * R * C;
    const float* inb = in + boff;
    __nv_bfloat16* hib = hi + boff;
    __nv_bfloat16* lob = lo + boff;
    int c0 = blockIdx.x * 32, r0 = blockIdx.y * 32;
    int tx = threadIdx.x;
#pragma unroll
    for (int i = threadIdx.y; i < 32; i += 8)
        tile[i][tx] = inb[(size_t)(r0 + i) * C + c0 + tx];
    __syncthreads();
#pragma unroll
    for (int i = threadIdx.y; i < 32; i += 8) {
        float v = tile[tx][i];
        __nv_bfloat16 h, l; split2(v, h, l);
        size_t o = (size_t)(c0 + i) * R + r0 + tx;
        hib[o] = h; lob[o] = l;
    }
}

// ---------------------------------------------------------------------------
// softmax over rows of 4096, fp32 in -> split bf16 out
// ---------------------------------------------------------------------------
__global__ __launch_bounds__(256)
void softmax_split(const float* __restrict__ sc,
                   __nv_bfloat16* __restrict__ ah,
                   __nv_bfloat16* __restrict__ al)
{
    __shared__ float sred[32];
    size_t roff = (size_t)blockIdx.x * BDIM;
    const float* p = sc + roff;
    const int tid = threadIdx.x;

    float v[16];
    float m = -3.0e38f;
#pragma unroll
    for (int i = 0; i < 16; i++) { v[i] = p[tid + 256 * i]; m = fmaxf(m, v[i]); }
#pragma unroll
    for (int o = 16; o > 0; o >>= 1) m = fmaxf(m, __shfl_xor_sync(0xffffffffu, m, o));
    if ((tid & 31) == 0) sred[tid >> 5] = m;
    __syncthreads();
    if (tid < 32) {
        float t = (tid < 8) ? sred[tid] : -3.0e38f;
#pragma unroll
        for (int o = 4; o > 0; o >>= 1) t = fmaxf(t, __shfl_xor_sync(0xffffffffu, t, o));
        if (tid == 0) sred[0] = t;
    }
    __syncthreads();
    m = sred[0];

    float s = 0.f;
#pragma unroll
    for (int i = 0; i < 16; i++) { v[i] = expf(v[i] - m); s += v[i]; }
#pragma unroll
    for (int o = 16; o > 0; o >>= 1) s += __shfl_xor_sync(0xffffffffu, s, o);
    __syncthreads();
    if ((tid & 31) == 0) sred[tid >> 5] = s;
    __syncthreads();
    if (tid < 32) {
        float t = (tid < 8) ? sred[tid] : 0.f;
#pragma unroll
        for (int o = 4; o > 0; o >>= 1) t += __shfl_xor_sync(0xffffffffu, t, o);
        if (tid == 0) sred[0] = t;
    }
    __syncthreads();
    float inv = 1.0f / sred[0];
#pragma unroll
    for (int i = 0; i < 16; i++) {
        float w = v[i] * inv;
        __nv_bfloat16 h, l; split2(w, h, l);
        ah[roff + tid + 256 * i] = h;
        al[roff + tid + 256 * i] = l;
    }
}

// ---------------------------------------------------------------------------
// Split-bf16 tensor-core GEMM: C = A * B (+ epilogue)
//   A: [M,K] row-major bf16 (hi/lo), B: [K,N] row-major bf16 (hi/lo)
//   acc = Ah*Bh + Ah*Bl + Al*Bh  (fp32 accumulators)
// EPI: 0 = fp32 store ; 1 = fp32 +bias ; 2 = split store ; 3 = split(resid + silu(acc+bias))
// Tiles: BM=BN=128, BK=32, 256 threads (8 warps of 64x32), cp.async double buffer
// ---------------------------------------------------------------------------
#define SM_AH 0
#define SM_AL 20480
#define SM_BH 40960
#define SM_BL 58368
#define SMEM_BYTES 75776
#define A_BUF 10240   // 128*40*2 bytes per buffer
#define B_BUF 8704    // 32*136*2

template<int EPI>
__global__ __launch_bounds__(256, 1)
void bgemm(const __nv_bfloat16* __restrict__ Ah, const __nv_bfloat16* __restrict__ Al,
           const __nv_bfloat16* __restrict__ Bh, const __nv_bfloat16* __restrict__ Bl,
           int M, int K, int N,
           long sA, long sB, long sC,
           float* __restrict__ Cf,
           __nv_bfloat16* __restrict__ Ch, __nv_bfloat16* __restrict__ Cl,
           const float* __restrict__ bias, const float* __restrict__ resid)
{
    extern __shared__ char smem[];
    const u32 sbase = (u32)__cvta_generic_to_shared(smem);

    const int bz = blockIdx.z;
    Ah += (size_t)bz * sA; Al += (size_t)bz * sA;
    Bh += (size_t)bz * sB; Bl += (size_t)bz * sB;
    if (EPI == 0 || EPI == 1) Cf += (size_t)bz * sC;
    else { Ch += (size_t)bz * sC; Cl += (size_t)bz * sC; }

    // CTA swizzle (GROUP_M = 8)
    const int tiles_n = gridDim.x, tiles_m = gridDim.y;
    int bid = blockIdx.x + blockIdx.y * tiles_n;
    const int G = 8;
    int gsz = G * tiles_n;
    int g   = bid / gsz;
    int rem = bid - g * gsz;
    int gm  = min(G, tiles_m - g * G);
    int m0  = (g * G + rem % gm) * 128;
    int n0  = (rem / gm) * 128;

    const int tid  = threadIdx.x;
    const int wid  = tid >> 5;
    const int lane = tid & 31;
    const int wm   = (wid & 1) * 64;   // warp m offset in tile
    const int wn   = (wid >> 1) * 32;  // warp n offset in tile

    float acc[4][4][4];
#pragma unroll
    for (int i = 0; i < 4; i++)
#pragma unroll
        for (int j = 0; j < 4; j++)
#pragma unroll
            for (int q = 0; q < 4; q++) acc[i][j][q] = 0.f;

    // ---- staging lambda (manual) ----
    // A chunks: 512 x 16B : chunk c -> row=c>>2 (0..127), kc=(c&3)*8
    // B chunks: 512 x 16B : chunk c -> row=c>>4 (0..31),  nc=(c&15)*8
    const int a_row = tid >> 2,        a_kc = (tid & 3) << 3;
    const int a_row2 = (tid + 256) >> 2, a_kc2 = ((tid + 256) & 3) << 3;
    const int b_row = tid >> 4,        b_nc = (tid & 15) << 3;
    const int b_row2 = (tid + 256) >> 4, b_nc2 = ((tid + 256) & 15) << 3;

    const int nk = K >> 5;

#define STAGE(buf, k0)  do {                                                              \
    u32 da1 = sbase + SM_AH + (buf)*A_BUF + (a_row*40  + a_kc )*2;                        \
    u32 da2 = sbase + SM_AH + (buf)*A_BUF + (a_row2*40 + a_kc2)*2;                        \
    const __nv_bfloat16* ga1 = Ah + (size_t)(m0 + a_row )*K + (k0) + a_kc;                \
    const __nv_bfloat16* ga2 = Ah + (size_t)(m0 + a_row2)*K + (k0) + a_kc2;               \
    cpa16(da1, ga1); cpa16(da2, ga2);                                                     \
    cpa16(da1 + (SM_AL-SM_AH), Al + (ga1 - Ah));                                          \
    cpa16(da2 + (SM_AL-SM_AH), Al + (ga2 - Ah));                                          \
    u32 db1 = sbase + SM_BH + (buf)*B_BUF + (b_row*136  + b_nc )*2;                       \
    u32 db2 = sbase + SM_BH + (buf)*B_BUF + (b_row2*136 + b_nc2)*2;                       \
    const __nv_bfloat16* gb1 = Bh + (size_t)((k0) + b_row )*N + n0 + b_nc;                \
    const __nv_bfloat16* gb2 = Bh + (size_t)((k0) + b_row2)*N + n0 + b_nc2;               \
    cpa16(db1, gb1); cpa16(db2, gb2);                                                     \
    cpa16(db1 + (SM_BL-SM_BH), Bl + (gb1 - Bh));                                          \
    cpa16(db2 + (SM_BL-SM_BH), Bl + (gb2 - Bh));                                          \
} while (0)

    STAGE(0, 0);
    cp_commit();

    // ldmatrix lane addressing components (bytes)
    const int aRowSel = lane & 15;                 // row within 16
    const int aColSel = (lane >> 4) << 3;          // 0 or 8 (k offset)
    const int bRowSel = (lane & 7) + (lane & 8);   // k row within 16
    const int bColSel = (lane & 16) >> 1;          // 0 or 8 (n offset)

    for (int kt = 0; kt < nk; kt++) {
        if (kt + 1 < nk) STAGE((kt + 1) & 1, (kt + 1) << 5);
        cp_commit();
        cp_wait1();
        __syncthreads();

        const int buf = kt & 1;
        const u32 abase = sbase + SM_AH + buf * A_BUF;
        const u32 bbase = sbase + SM_BH + buf * B_BUF;

#pragma unroll
        for (int kk = 0; kk < 32; kk += 16) {
            u32 ah[4][4], al[4][4], bh[2][4], bl[2][4];
#pragma unroll
            for (int i = 0; i < 4; i++) {
                u32 off = ((wm + i * 16 + aRowSel) * 40 + kk + aColSel) * 2;
                ldsm_x4(ah[i], abase + off);
                ldsm_x4(al[i], abase + off + (SM_AL - SM_AH));
            }
#pragma unroll
            for (int j2 = 0; j2 < 2; j2++) {
                u32 off = ((kk + bRowSel) * 136 + wn + j2 * 16 + bColSel) * 2;
                ldsm_x4t(bh[j2], bbase + off);
                ldsm_x4t(bl[j2], bbase + off + (SM_BL - SM_BH));
            }
#pragma unroll
            for (int i = 0; i < 4; i++)
#pragma unroll
                for (int j = 0; j < 4; j++) {
                    const u32* bhp = &bh[j >> 1][(j & 1) * 2];
                    const u32* blp = &bl[j >> 1][(j & 1) * 2];
                    mma16816(acc[i][j], ah[i], bhp);
                    mma16816(acc[i][j], ah[i], blp);
                    mma16816(acc[i][j], al[i], bhp);
                }
        }
        __syncthreads();
    }

    // ---- epilogue ----
#pragma unroll
    for (int mi = 0; mi < 4; mi++) {
#pragma unroll
        for (int p = 0; p < 2; p++) {
            int r = m0 + wm + mi * 16 + (lane >> 2) + p * 8;
            size_t rowoff = (size_t)r * N;
#pragma unroll
            for (int nj = 0; nj < 4; nj++) {
                int c = n0 + wn + nj * 8 + (lane & 3) * 2;
                float v0 = acc[mi][nj][p * 2 + 0];
                float v1 = acc[mi][nj][p * 2 + 1];
                if (EPI == 1 || EPI == 3) { v0 += bias[c]; v1 += bias[c + 1]; }
                if (EPI == 3) {
                    float r0 = resid[rowoff + c], r1 = resid[rowoff + c + 1];
                    v0 = r0 + v0 / (1.f + expf(-v0));
                    v1 = r1 + v1 / (1.f + expf(-v1));
                }
                if (EPI == 0 || EPI == 1) {
                    *reinterpret_cast<float2*>(Cf + rowoff + c) = make_float2(v0, v1);
                } else {
                    __nv_bfloat16 h0, l0, h1, l1;
                    split2(v0, h0, l0); split2(v1, h1, l1);
                    *reinterpret_cast<__nv_bfloat162*>(Ch + rowoff + c) = __halves2bfloat162(h0, h1);
                    *reinterpret_cast<__nv_bfloat162*>(Cl + rowoff + c) = __halves2bfloat162(l0, l1);
                }
            }
        }
    }
#undef STAGE
}

// ---------------------------------------------------------------------------
// launcher
// ---------------------------------------------------------------------------
extern "C" void kernel_launch(void* const* d_in, const int* in_sizes, int n_in,
                              void* d_out, int out_size)
{
    const float* x    = (const float*)d_in[0];
    const float* W1   = (const float*)d_in[1];
    const float* W2   = (const float*)d_in[2];
    const float* W4   = (const float*)d_in[3];
    const float* b4   = (const float*)d_in[4];
    const float* Wout = (const float*)d_in[5];
    const float* bout = (const float*)d_in[6];
    float* out = (float*)d_out;

    float *xA, *sc;
    __nv_bfloat16 *sx, *w1, *w2, *w4, *wo, *xAT, *xB, *at, *xO, *t;
    cudaGetSymbolAddress((void**)&xA,  g_xA);
    cudaGetSymbolAddress((void**)&sc,  g_sc);
    cudaGetSymbolAddress((void**)&sx,  s_x);
    cudaGetSymbolAddress((void**)&w1,  s_w1);
    cudaGetSymbolAddress((void**)&w2,  s_w2);
    cudaGetSymbolAddress((void**)&w4,  s_w4);
    cudaGetSymbolAddress((void**)&wo,  s_wo);
    cudaGetSymbolAddress((void**)&xAT, s_xAT);
    cudaGetSymbolAddress((void**)&xB,  s_xB);
    cudaGetSymbolAddress((void**)&at,  s_at);
    cudaGetSymbolAddress((void**)&xO,  s_xO);
    cudaGetSymbolAddress((void**)&t,   s_t);

    cudaFuncSetAttribute(bgemm<0>, cudaFuncAttributeMaxDynamicSharedMemorySize, SMEM_BYTES);
    cudaFuncSetAttribute(bgemm<1>, cudaFuncAttributeMaxDynamicSharedMemorySize, SMEM_BYTES);
    cudaFuncSetAttribute(bgemm<2>, cudaFuncAttributeMaxDynamicSharedMemorySize, SMEM_BYTES);
    cudaFuncSetAttribute(bgemm<3>, cudaFuncAttributeMaxDynamicSharedMemorySize, SMEM_BYTES);

    // 1) split x ; split+transpose weights
    split_rm<<<(unsigned)((PLANE_X / 4 + 255) / 256), 256>>>(x, sx, sx + PLANE_X, PLANE_X / 4);
    {
        dim3 g(128, 128, 1), b(32, 8, 1);
        split_tr<<<g, b>>>(W1,   w1, w1 + PLANE_W, BDIM, BDIM);
        split_tr<<<g, b>>>(W2,   w2, w2 + PLANE_W, BDIM, BDIM);
        split_tr<<<g, b>>>(W4,   w4, w4 + PLANE_W, BDIM, BDIM);
        split_tr<<<g, b>>>(Wout, wo, wo + PLANE_W, BDIM, BDIM);
    }

    // 2) xA (fp32) and xB (split) projections: [4096,4096,4096]
    {
        dim3 g(32, 32, 1);
        bgemm<0><<<g, 256, SMEM_BYTES>>>(sx, sx + PLANE_X, w1, w1 + PLANE_W,
                                         MTOK, BDIM, BDIM, 0, 0, 0,
                                         xA, nullptr, nullptr, nullptr, nullptr);
        bgemm<2><<<g, 256, SMEM_BYTES>>>(sx, sx + PLANE_X, w2, w2 + PLANE_W,
                                         MTOK, BDIM, BDIM, 0, 0, 0,
                                         nullptr, xB, xB + PLANE_X, nullptr, nullptr);
    }

    // 3) transpose+split xA per batch: [S,D] -> [D,S]
    split_tr<<<dim3(128, 64, NB), dim3(32, 8, 1)>>>(xA, xAT, xAT + PLANE_AT, SEQ, BDIM);

    // 4) scores[b] = xAT[b] @ xB[b] : M=4096, K=2048, N=4096
    bgemm<0><<<dim3(32, 32, NB), 256, SMEM_BYTES>>>(
        xAT, xAT + PLANE_AT, xB, xB + PLANE_X,
        BDIM, SEQ, BDIM,
        (long)BDIM * SEQ, (long)SEQ * BDIM, (long)BDIM * BDIM,
        sc, nullptr, nullptr, nullptr, nullptr);

    // 5) softmax rows -> split attn
    softmax_split<<<NB * BDIM, 256>>>(sc, at, at + PLANE_SC);

    // 6) xO[b] = x[b] @ attn[b] : M=2048, K=4096, N=4096
    bgemm<2><<<dim3(32, 16, NB), 256, SMEM_BYTES>>>(
        sx, sx + PLANE_X, at, at + PLANE_SC,
        SEQ, BDIM, BDIM,
        (long)SEQ * BDIM, (long)BDIM * BDIM, (long)SEQ * BDIM,
        nullptr, xO, xO + PLANE_X, nullptr, nullptr);

    // 7) t = split(x + silu(xO @ W4^T + b4)) : M=4096
    bgemm<3><<<dim3(32, 32, 1), 256, SMEM_BYTES>>>(
        xO, xO + PLANE_X, w4, w4 + PLANE_W,
        MTOK, BDIM, BDIM, 0, 0, 0,
        nullptr, t, t + PLANE_X, b4, x);

    // 8) out = t @ Wout^T + bout
    bgemm<1><<<dim3(32, 32, 1), 256, SMEM_BYTES>>>(
        t, t + PLANE_X, wo, wo + PLANE_W,
        MTOK, BDIM, BDIM, 0, 0, 0,
        out, nullptr, nullptr, bout, nullptr);
}

// round 4
// speedup vs baseline: 2.8078x; 1.0213x over previous
#include <cuda_runtime.h>
#include <cuda_bf16.h>
#include <math.h>

#define BDIM 4096
#define SEQ  2048
#define NB   2
#define MTOK 4096

typedef unsigned int u32;

// ---------------------------------------------------------------------------
// Static scratch
// ---------------------------------------------------------------------------
__device__ float g_xA[(size_t)NB * SEQ * BDIM];    // fp32 xA (needs transpose)
__device__ float g_sc[(size_t)NB * BDIM * BDIM];   // fp32 scores

static const size_t PLANE_X  = (size_t)MTOK * BDIM;
static const size_t PLANE_W  = (size_t)BDIM * BDIM;
static const size_t PLANE_AT = (size_t)NB * BDIM * SEQ;
static const size_t PLANE_SC = (size_t)NB * BDIM * BDIM;

__device__ __nv_bfloat16 s_x  [2 * PLANE_X];   // x split (hi, lo planes)
__device__ __nv_bfloat16 s_w1 [2 * PLANE_W];   // W1^T split ([K,N])
__device__ __nv_bfloat16 s_w2 [2 * PLANE_W];
__device__ __nv_bfloat16 s_w4 [2 * PLANE_W];
__device__ __nv_bfloat16 s_wo [2 * PLANE_W];
__device__ __nv_bfloat16 s_xAT[2 * PLANE_AT];  // xA^T split [b][D][S]
__device__ __nv_bfloat16 s_xB [2 * PLANE_X];   // xB split [b][S][D]
__device__ __nv_bfloat16 s_at [2 * PLANE_SC];  // attn split [b][D][D]
__device__ __nv_bfloat16 s_xO [2 * PLANE_X];
__device__ __nv_bfloat16 s_t  [2 * PLANE_X];

// ---------------------------------------------------------------------------
// helpers
// ---------------------------------------------------------------------------
__device__ __forceinline__ void split2(float v, __nv_bfloat16& h, __nv_bfloat16& l) {
    h = __float2bfloat16(v);
    l = __float2bfloat16(v - __bfloat162float(h));
}
__device__ __forceinline__ void cpa16(u32 dst, const void* src) {
    asm volatile("cp.async.cg.shared.global [%0], [%1], 16;\n" :: "r"(dst), "l"(src));
}
__device__ __forceinline__ void cp_commit() { asm volatile("cp.async.commit_group;\n"); }

__device__ __forceinline__ void ldsm_x4(u32* r, u32 addr) {
    asm volatile("ldmatrix.sync.aligned.m8n8.x4.shared.b16 {%0,%1,%2,%3}, [%4];\n"
                 : "=r"(r[0]), "=r"(r[1]), "=r"(r[2]), "=r"(r[3]) : "r"(addr));
}
__device__ __forceinline__ void ldsm_x4t(u32* r, u32 addr) {
    asm volatile("ldmatrix.sync.aligned.m8n8.x4.trans.shared.b16 {%0,%1,%2,%3}, [%4];\n"
                 : "=r"(r[0]), "=r"(r[1]), "=r"(r[2]), "=r"(r[3]) : "r"(addr));
}
__device__ __forceinline__ void mma16816(float* d, const u32* a, const u32* b) {
    asm volatile("mma.sync.aligned.m16n8k16.row.col.f32.bf16.bf16.f32 "
                 "{%0,%1,%2,%3}, {%4,%5,%6,%7}, {%8,%9}, {%0,%1,%2,%3};\n"
                 : "+f"(d[0]), "+f"(d[1]), "+f"(d[2]), "+f"(d[3])
                 : "r"(a[0]), "r"(a[1]), "r"(a[2]), "r"(a[3]), "r"(b[0]), "r"(b[1]));
}

// ---------------------------------------------------------------------------
// split kernels
// ---------------------------------------------------------------------------
__global__ void split_rm(const float* __restrict__ in,
                         __nv_bfloat16* __restrict__ hi,
                         __nv_bfloat16* __restrict__ lo, size_t n4)
{
    size_t i = (size_t)blockIdx.x * blockDim.x + threadIdx.x;
    if (i >= n4) return;
    float4 v = reinterpret_cast<const float4*>(in)[i];
    __nv_bfloat16 h0,l0,h1,l1,h2,l2,h3,l3;
    split2(v.x,h0,l0); split2(v.y,h1,l1); split2(v.z,h2,l2); split2(v.w,h3,l3);
    reinterpret_cast<__nv_bfloat162*>(hi)[2*i+0] = __halves2bfloat162(h0,h1);
    reinterpret_cast<__nv_bfloat162*>(hi)[2*i+1] = __halves2bfloat162(h2,h3);
    reinterpret_cast<__nv_bfloat162*>(lo)[2*i+0] = __halves2bfloat162(l0,l1);
    reinterpret_cast<__nv_bfloat162*>(lo)[2*i+1] = __halves2bfloat162(l2,l3);
}

// in: [R,C] fp32 -> out hi/lo: [C,R] bf16   (batched via blockIdx.z)
__global__ void split_tr(const float* __restrict__ in,
                         __nv_bfloat16* __restrict__ hi,
                         __nv_bfloat16* __restrict__ lo, int R, int C)
{
    __shared__ float tile[32][33];
    size_t boff = (size_t)blockIdx.z * R * C;
    const float* inb = in + boff;
    __nv_bfloat16* hib = hi + boff;
    __nv_bfloat16* lob = lo + boff;
    int c0 = blockIdx.x * 32, r0 = blockIdx.y * 32;
    int tx = threadIdx.x;
#pragma unroll
    for (int i = threadIdx.y; i < 32; i += 8)
        tile[i][tx] = inb[(size_t)(r0 + i) * C + c0 + tx];
    __syncthreads();
#pragma unroll
    for (int i = threadIdx.y; i < 32; i += 8) {
        float v = tile[tx][i];
        __nv_bfloat16 h, l; split2(v, h, l);
        size_t o = (size_t)(c0 + i) * R + r0 + tx;
        hib[o] = h; lob[o] = l;
    }
}

// softmax rows of 4096, fp32 in -> split bf16 out
__global__ __launch_bounds__(256)
void softmax_split(const float* __restrict__ sc,
                   __nv_bfloat16* __restrict__ ah,
                   __nv_bfloat16* __restrict__ al)
{
    __shared__ float sred[32];
    size_t roff = (size_t)blockIdx.x * BDIM;
    const float* p = sc + roff;
    const int tid = threadIdx.x;

    float v[16];
    float m = -3.0e38f;
#pragma unroll
    for (int i = 0; i < 16; i++) { v[i] = p[tid + 256 * i]; m = fmaxf(m, v[i]); }
#pragma unroll
    for (int o = 16; o > 0; o >>= 1) m = fmaxf(m, __shfl_xor_sync(0xffffffffu, m, o));
    if ((tid & 31) == 0) sred[tid >> 5] = m;
    __syncthreads();
    if (tid < 32) {
        float t = (tid < 8) ? sred[tid] : -3.0e38f;
#pragma unroll
        for (int o = 4; o > 0; o >>= 1) t = fmaxf(t, __shfl_xor_sync(0xffffffffu, t, o));
        if (tid == 0) sred[0] = t;
    }
    __syncthreads();
    m = sred[0];

    float s = 0.f;
#pragma unroll
    for (int i = 0; i < 16; i++) { v[i] = expf(v[i] - m); s += v[i]; }
#pragma unroll
    for (int o = 16; o > 0; o >>= 1) s += __shfl_xor_sync(0xffffffffu, s, o);
    __syncthreads();
    if ((tid & 31) == 0) sred[tid >> 5] = s;
    __syncthreads();
    if (tid < 32) {
        float t = (tid < 8) ? sred[tid] : 0.f;
#pragma unroll
        for (int o = 4; o > 0; o >>= 1) t += __shfl_xor_sync(0xffffffffu, t, o);
        if (tid == 0) sred[0] = t;
    }
    __syncthreads();
    float inv = 1.0f / sred[0];
#pragma unroll
    for (int i = 0; i < 16; i++) {
        float w = v[i] * inv;
        __nv_bfloat16 h, l; split2(w, h, l);
        ah[roff + tid + 256 * i] = h;
        al[roff + tid + 256 * i] = l;
    }
}

// ---------------------------------------------------------------------------
// Split-bf16 tensor-core GEMM v2: C = A * B (+ epilogue)
//   A: [M,K] row-major split, B: [K,N] row-major split
//   acc = Ah*Bh + Ah*Bl + Al*Bh (fp32)
// CTA tile 128x256, warp tile 64x64, 8 warps, BK=32, 3-stage cp.async pipeline.
// EPI: 0 fp32 | 1 fp32+bias | 2 split | 3 split(resid + silu(acc+bias))
// ---------------------------------------------------------------------------
#define A_PITCH 40
#define B_PITCH 264
#define A_BUF   (128 * A_PITCH * 2)              // 10240 B per plane
#define B_BUF   (32 * B_PITCH * 2)               // 16896 B per plane
#define SOFF_AL (A_BUF)
#define SOFF_BH (2 * A_BUF)
#define SOFF_BL (2 * A_BUF + B_BUF)
#define STAGE_BYTES (2 * A_BUF + 2 * B_BUF)      // 54272
#define SMEM_B2 (3 * STAGE_BYTES)                // 162816

template<int EPI>
__global__ __launch_bounds__(256, 1)
void bgemm(const __nv_bfloat16* __restrict__ Ah, const __nv_bfloat16* __restrict__ Al,
           const __nv_bfloat16* __restrict__ Bh, const __nv_bfloat16* __restrict__ Bl,
           int K, int N,
           long sA, long sB, long sC,
           float* __restrict__ Cf,
           __nv_bfloat16* __restrict__ Ch, __nv_bfloat16* __restrict__ Cl,
           const float* __restrict__ bias, const float* __restrict__ resid)
{
    extern __shared__ __align__(16) char smem[];
    const u32 sbase = (u32)__cvta_generic_to_shared(smem);

    const int bz = blockIdx.z;
    Ah += (size_t)bz * sA; Al += (size_t)bz * sA;
    Bh += (size_t)bz * sB; Bl += (size_t)bz * sB;
    if (EPI == 0 || EPI == 1) Cf += (size_t)bz * sC;
    else { Ch += (size_t)bz * sC; Cl += (size_t)bz * sC; }

    // CTA swizzle (GROUP_M = 8)
    const int tiles_n = gridDim.x, tiles_m = gridDim.y;
    int bid = blockIdx.x + blockIdx.y * tiles_n;
    const int G = 8;
    int gsz = G * tiles_n;
    int g   = bid / gsz;
    int rem = bid - g * gsz;
    int gm  = min(G, tiles_m - g * G);
    const int m0 = (g * G + rem % gm) * 128;
    const int n0 = (rem / gm) * 256;

    const int tid  = threadIdx.x;
    const int wid  = tid >> 5;
    const int lane = tid & 31;
    const int wm   = (wid & 1) * 64;
    const int wn   = (wid >> 1) * 64;

    float acc[4][8][4];
#pragma unroll
    for (int i = 0; i < 4; i++)
#pragma unroll
        for (int j = 0; j < 8; j++)
#pragma unroll
            for (int q = 0; q < 4; q++) acc[i][j][q] = 0.f;

    // staging decomposition
    const int a_row0 = tid >> 2,          a_kc0 = (tid & 3) << 3;
    const int a_row1 = (tid + 256) >> 2,  a_kc1 = ((tid + 256) & 3) << 3;

    const int nk = K >> 5;

#define STAGE(buf, k0) do {                                                         \
    u32 sb_ = sbase + (buf) * STAGE_BYTES;                                          \
    {                                                                               \
        u32 d0 = sb_ + (u32)(a_row0 * A_PITCH + a_kc0) * 2;                         \
        u32 d1 = sb_ + (u32)(a_row1 * A_PITCH + a_kc1) * 2;                         \
        const __nv_bfloat16* g0 = Ah + (size_t)(m0 + a_row0) * K + (k0) + a_kc0;    \
        const __nv_bfloat16* g1 = Ah + (size_t)(m0 + a_row1) * K + (k0) + a_kc1;    \
        cpa16(d0, g0); cpa16(d1, g1);                                               \
        cpa16(d0 + SOFF_AL, Al + (g0 - Ah));                                        \
        cpa16(d1 + SOFF_AL, Al + (g1 - Ah));                                        \
    }                                                                               \
    _Pragma("unroll")                                                               \
    for (int r_ = 0; r_ < 4; r_++) {                                                \
        int c_  = tid + (r_ << 8);                                                  \
        int br_ = c_ >> 5, bn_ = (c_ & 31) << 3;                                    \
        u32 d_  = sb_ + SOFF_BH + (u32)(br_ * B_PITCH + bn_) * 2;                   \
        const __nv_bfloat16* gb_ = Bh + (size_t)((k0) + br_) * N + n0 + bn_;        \
        cpa16(d_, gb_);                                                             \
        cpa16(d_ + B_BUF, Bl + (gb_ - Bh));                                         \
    }                                                                               \
} while (0)

    STAGE(0, 0);
    cp_commit();
    STAGE(1, 32);
    cp_commit();

    // ldmatrix lane selectors
    const int aRowSel = lane & 15;
    const int aColSel = (lane >> 4) << 3;
    const int bRowSel = (lane & 7) + (lane & 8);
    const int bColSel = (lane & 16) >> 1;

    for (int kt = 0; kt < nk; kt++) {
        asm volatile("cp.async.wait_group 1;");
        __syncthreads();

        if (kt + 2 < nk) STAGE((kt + 2) % 3, (kt + 2) << 5);
        cp_commit();

        const u32 ab = sbase + (u32)(kt % 3) * STAGE_BYTES;
        const u32 bb = ab + SOFF_BH;

#pragma unroll
        for (int kk = 0; kk < 32; kk += 16) {
            u32 ah[4][4], al[4][4];
#pragma unroll
            for (int i = 0; i < 4; i++) {
                u32 off = (u32)((wm + i * 16 + aRowSel) * A_PITCH + kk + aColSel) * 2;
                ldsm_x4(ah[i], ab + off);
                ldsm_x4(al[i], ab + SOFF_AL + off);
            }
#pragma unroll
            for (int j2 = 0; j2 < 4; j2++) {
                u32 bh[4], bl[4];
                u32 off = (u32)((kk + bRowSel) * B_PITCH + wn + j2 * 16 + bColSel) * 2;
                ldsm_x4t(bh, bb + off);
                ldsm_x4t(bl, bb + (SOFF_BL - SOFF_BH) + off);
#pragma unroll
                for (int jj = 0; jj < 2; jj++) {
                    const u32* bhp = &bh[jj * 2];
                    const u32* blp = &bl[jj * 2];
#pragma unroll
                    for (int i = 0; i < 4; i++) {
                        float* a_ = acc[i][j2 * 2 + jj];
                        mma16816(a_, ah[i], bhp);
                        mma16816(a_, ah[i], blp);
                        mma16816(a_, al[i], bhp);
                    }
                }
            }
        }
    }

    // ---- epilogue ----
#pragma unroll
    for (int mi = 0; mi < 4; mi++) {
#pragma unroll
        for (int p = 0; p < 2; p++) {
            int r = m0 + wm + mi * 16 + (lane >> 2) + p * 8;
            size_t rowoff = (size_t)r * N;
#pragma unroll
            for (int nj = 0; nj < 8; nj++) {
                int c = n0 + wn + nj * 8 + (lane & 3) * 2;
                float v0 = acc[mi][nj][p * 2 + 0];
                float v1 = acc[mi][nj][p * 2 + 1];
                if (EPI == 1 || EPI == 3) { v0 += bias[c]; v1 += bias[c + 1]; }
                if (EPI == 3) {
                    float r0 = resid[rowoff + c], r1 = resid[rowoff + c + 1];
                    v0 = r0 + v0 / (1.f + expf(-v0));
                    v1 = r1 + v1 / (1.f + expf(-v1));
                }
                if (EPI == 0 || EPI == 1) {
                    *reinterpret_cast<float2*>(Cf + rowoff + c) = make_float2(v0, v1);
                } else {
                    __nv_bfloat16 h0, l0, h1, l1;
                    split2(v0, h0, l0); split2(v1, h1, l1);
                    *reinterpret_cast<__nv_bfloat162*>(Ch + rowoff + c) = __halves2bfloat162(h0, h1);
                    *reinterpret_cast<__nv_bfloat162*>(Cl + rowoff + c) = __halves2bfloat162(l0, l1);
                }
            }
        }
    }
#undef STAGE
}

// ---------------------------------------------------------------------------
// launcher
// ---------------------------------------------------------------------------
extern "C" void kernel_launch(void* const* d_in, const int* in_sizes, int n_in,
                              void* d_out, int out_size)
{
    const float* x    = (const float*)d_in[0];
    const float* W1   = (const float*)d_in[1];
    const float* W2   = (const float*)d_in[2];
    const float* W4   = (const float*)d_in[3];
    const float* b4   = (const float*)d_in[4];
    const float* Wout = (const float*)d_in[5];
    const float* bout = (const float*)d_in[6];
    float* out = (float*)d_out;

    float *xA, *sc;
    __nv_bfloat16 *sx, *w1, *w2, *w4, *wo, *xAT, *xB, *at, *xO, *t;
    cudaGetSymbolAddress((void**)&xA,  g_xA);
    cudaGetSymbolAddress((void**)&sc,  g_sc);
    cudaGetSymbolAddress((void**)&sx,  s_x);
    cudaGetSymbolAddress((void**)&w1,  s_w1);
    cudaGetSymbolAddress((void**)&w2,  s_w2);
    cudaGetSymbolAddress((void**)&w4,  s_w4);
    cudaGetSymbolAddress((void**)&wo,  s_wo);
    cudaGetSymbolAddress((void**)&xAT, s_xAT);
    cudaGetSymbolAddress((void**)&xB,  s_xB);
    cudaGetSymbolAddress((void**)&at,  s_at);
    cudaGetSymbolAddress((void**)&xO,  s_xO);
    cudaGetSymbolAddress((void**)&t,   s_t);

    cudaFuncSetAttribute(bgemm<0>, cudaFuncAttributeMaxDynamicSharedMemorySize, SMEM_B2);
    cudaFuncSetAttribute(bgemm<1>, cudaFuncAttributeMaxDynamicSharedMemorySize, SMEM_B2);
    cudaFuncSetAttribute(bgemm<2>, cudaFuncAttributeMaxDynamicSharedMemorySize, SMEM_B2);
    cudaFuncSetAttribute(bgemm<3>, cudaFuncAttributeMaxDynamicSharedMemorySize, SMEM_B2);

    // splits: x row-major; weights transposed to [K,N]
    split_rm<<<(unsigned)((PLANE_X / 4 + 255) / 256), 256>>>(x, sx, sx + PLANE_X, PLANE_X / 4);
    {
        dim3 g(128, 128, 1), b(32, 8, 1);
        split_tr<<<g, b>>>(W1,   w1, w1 + PLANE_W, BDIM, BDIM);
        split_tr<<<g, b>>>(W2,   w2, w2 + PLANE_W, BDIM, BDIM);
        split_tr<<<g, b>>>(W4,   w4, w4 + PLANE_W, BDIM, BDIM);
        split_tr<<<g, b>>>(Wout, wo, wo + PLANE_W, BDIM, BDIM);
    }

    // xA (fp32) and xB (split) projections: M=4096, K=4096, N=4096
    {
        dim3 g(16, 32, 1);
        bgemm<0><<<g, 256, SMEM_B2>>>(sx, sx + PLANE_X, w1, w1 + PLANE_W,
                                      BDIM, BDIM, 0, 0, 0,
                                      xA, nullptr, nullptr, nullptr, nullptr);
        bgemm<2><<<g, 256, SMEM_B2>>>(sx, sx + PLANE_X, w2, w2 + PLANE_W,
                                      BDIM, BDIM, 0, 0, 0,
                                      nullptr, xB, xB + PLANE_X, nullptr, nullptr);
    }

    // transpose+split xA per batch: [S,D] -> [D,S]
    split_tr<<<dim3(128, 64, NB), dim3(32, 8, 1)>>>(xA, xAT, xAT + PLANE_AT, SEQ, BDIM);

    // scores[b] = xAT[b] @ xB[b] : M=4096, K=2048, N=4096
    bgemm<0><<<dim3(16, 32, NB), 256, SMEM_B2>>>(
        xAT, xAT + PLANE_AT, xB, xB + PLANE_X,
        SEQ, BDIM,
        (long)BDIM * SEQ, (long)SEQ * BDIM, (long)BDIM * BDIM,
        sc, nullptr, nullptr, nullptr, nullptr);

    // softmax rows -> split attn
    softmax_split<<<NB * BDIM, 256>>>(sc, at, at + PLANE_SC);

    // xO[b] = x[b] @ attn[b] : M=2048, K=4096, N=4096
    bgemm<2><<<dim3(16, 16, NB), 256, SMEM_B2>>>(
        sx, sx + PLANE_X, at, at + PLANE_SC,
        BDIM, BDIM,
        (long)SEQ * BDIM, (long)BDIM * BDIM, (long)SEQ * BDIM,
        nullptr, xO, xO + PLANE_X, nullptr, nullptr);

    // t = split(x + silu(xO @ W4^T + b4)) : M=4096
    bgemm<3><<<dim3(16, 32, 1), 256, SMEM_B2>>>(
        xO, xO + PLANE_X, w4, w4 + PLANE_W,
        BDIM, BDIM, 0, 0, 0,
        nullptr, t, t + PLANE_X, b4, x);

    // out = t @ Wout^T + bout
    bgemm<1><<<dim3(16, 32, 1), 256, SMEM_B2>>>(
        t, t + PLANE_X, wo, wo + PLANE_W,
        BDIM, BDIM, 0, 0, 0,
        out, nullptr, nullptr, bout, nullptr);
}